// round 15
// baseline (speedup 1.0000x reference)
#include <cuda_runtime.h>
#include <cuda_bf16.h>
#include <math.h>

// DynamicRouter: logits = x @ W^T + b + 0.1*noise ; top-2 ; sparse softmax.
// x[B=8,S=4096,D=768] f32, W[E=8,D=768] f32, b[8] f32, noise[B,S,8] f32.
//
// R15: direct-LDG A/B register double-buffer (no x smem traffic -> crossbar
// 8KB/token, only W LDS) at TOK=3 so regs fit 64 -> 4 CTAs/SM (32 warps),
// plus 2-chunk-ahead L2 prefetch. First config combining high occupancy with
// low crossbar pressure and continuous in-flight loads.

#define D_DIM        768
#define E_DIM        8
#define TOK_PER_WARP 3
#define WARPS        8
#define BLOCK        (WARPS * 32)
#define TOK_PER_BLK  (WARPS * TOK_PER_WARP)   // 24
#define D4           (D_DIM / 4)              // 192
#define NCHUNK       (D4 / 32)                // 6
#define NOISE_STD    0.1f

#define PREFETCH_L2(addr) \
    asm volatile("prefetch.global.L2 [%0];" :: "l"(addr))

__global__ __launch_bounds__(BLOCK, 4)
void router_kernel(const float* __restrict__ x,
                   const float* __restrict__ W,
                   const float* __restrict__ b,
                   const float* __restrict__ noise,
                   float* __restrict__ out,
                   int nTokens, int writeIdx)
{
    __shared__ float4 sW4[E_DIM * D4];   // 24 KB, 16B lane stride: conflict-free

    const int tid  = threadIdx.x;
    const int lane = tid & 31;
    const int wid  = tid >> 5;

    // Stage W into shared once (coalesced float4 copy of contiguous 24 KB)
    {
        const float4* Wg = reinterpret_cast<const float4*>(W);
        #pragma unroll
        for (int i = 0; i < (E_DIM * D4) / BLOCK; i++)
            sW4[i * BLOCK + tid] = Wg[i * BLOCK + tid];
    }
    __syncthreads();

    const int tokBase = blockIdx.x * TOK_PER_BLK + wid * TOK_PER_WARP;
    if (tokBase >= nTokens) return;

    // Clamped base (partial last warp recomputes last 3 valid tokens; stores
    // are masked below so duplicates are discarded).
    int tkClamp = tokBase;
    if (tkClamp > nTokens - TOK_PER_WARP) tkClamp = nTokens - TOK_PER_WARP;
    const float4* x4 = reinterpret_cast<const float4*>(x) + (size_t)tkClamp * D4;

    // L2 prefetch of one whole chunk (3 tokens x 4 lines) with one warp instr
    auto pf = [&](int c) {
        if (lane < 12) {
            const float4* a = x4 + (size_t)(lane >> 2) * D4 + c * 32 + (lane & 3) * 8;
            PREFETCH_L2(a);
        }
    };

    auto loadChunk = [&](float4* buf, int c) {
        #pragma unroll
        for (int t = 0; t < TOK_PER_WARP; t++)
            buf[t] = x4[(size_t)t * D4 + c * 32 + lane];   // coalesced 512B/token
    };

    float acc[TOK_PER_WARP * E_DIM];    // 24 regs
    #pragma unroll
    for (int v = 0; v < TOK_PER_WARP * E_DIM; v++) acc[v] = 0.0f;

    auto computeChunk = [&](const float4* buf, int c) {
        const int p = c * 32 + lane;
        #pragma unroll
        for (int e = 0; e < E_DIM; e++) {
            const float4 wv = sW4[e * D4 + p];             // LDS.128, reused x3
            #pragma unroll
            for (int t = 0; t < TOK_PER_WARP; t++)
                acc[t * E_DIM + e] += buf[t].x * wv.x + buf[t].y * wv.y
                                    + buf[t].z * wv.z + buf[t].w * wv.w;
        }
    };

    // A/B double-buffer, fully unrolled, 2-chunk-ahead L2 prefetch, no rotates
    float4 bufA[TOK_PER_WARP], bufB[TOK_PER_WARP];
    loadChunk(bufA, 0);
    pf(1);
    loadChunk(bufB, 1);  pf(2); computeChunk(bufA, 0);
    loadChunk(bufA, 2);  pf(3); computeChunk(bufB, 1);
    loadChunk(bufB, 3);  pf(4); computeChunk(bufA, 2);
    loadChunk(bufA, 4);  pf(5); computeChunk(bufB, 3);
    loadChunk(bufB, 5);          computeChunk(bufA, 4);
                                 computeChunk(bufB, 5);

    // Zero-pad to 32 slots, then log-halving butterfly: lane l ends with the
    // full 32-lane sum of slot l (slot v = t*8 + e for v < 24).
    float red[32];
    #pragma unroll
    for (int v = 0; v < TOK_PER_WARP * E_DIM; v++) red[v] = acc[v];
    #pragma unroll
    for (int v = TOK_PER_WARP * E_DIM; v < 32; v++) red[v] = 0.0f;

    #pragma unroll
    for (int m = 16; m >= 1; m >>= 1) {
        const bool upper = (lane & m) != 0;
        #pragma unroll
        for (int i = 0; i < m; i++) {
            const float lo = red[i], hi = red[i + m];
            const float send = upper ? lo : hi;
            const float recv = __shfl_xor_sync(0xFFFFFFFFu, send, m);
            red[i] = upper ? (hi + recv) : (lo + recv);
        }
    }
    const float sum = red[0];

    const int t = lane >> 3;            // slot token (0..3; only 0..2 valid)
    const int e = lane & 7;             // expert
    const long tok = (long)tkClamp + t;
    const bool valid = (lane < TOK_PER_WARP * E_DIM) && (tok < nTokens)
                     && (tok >= tokBase);   // discard clamp duplicates

    const float nval = valid ? __ldg(noise + (size_t)tkClamp * E_DIM + lane) : 0.0f;
    const float logit = sum + __ldg(b + e) + NOISE_STD * nval;

    // top-1 over each 8-lane expert group (ties -> lower index, jax top_k)
    float v1 = logit; int i1 = e;
    #pragma unroll
    for (int off = 1; off < 8; off <<= 1) {
        const float ov = __shfl_xor_sync(0xFFFFFFFFu, v1, off);
        const int   oi = __shfl_xor_sync(0xFFFFFFFFu, i1, off);
        if (ov > v1 || (ov == v1 && oi < i1)) { v1 = ov; i1 = oi; }
    }
    // top-2: exclude winner, reduce again
    float v2 = (e == i1) ? -INFINITY : logit; int i2 = e;
    #pragma unroll
    for (int off = 1; off < 8; off <<= 1) {
        const float ov = __shfl_xor_sync(0xFFFFFFFFu, v2, off);
        const int   oi = __shfl_xor_sync(0xFFFFFFFFu, i2, off);
        if (ov > v2 || (ov == v2 && oi < i2)) { v2 = ov; i2 = oi; }
    }

    // 2-element softmax (arg <= 0, no overflow)
    const float ed  = __expf(v2 - v1);
    const float inv = 1.0f / (1.0f + ed);
    const float p   = (e == i1) ? inv : ((e == i2) ? ed * inv : 0.0f);

    if (valid) {
        out[(size_t)tkClamp * E_DIM + lane] = p;   // 96B contiguous per warp
        if (writeIdx && e == 0) {
            float* idxOut = out + (size_t)nTokens * E_DIM;
            idxOut[tok * 2 + 0] = (float)i1;
            idxOut[tok * 2 + 1] = (float)i2;
        }
    }
}

extern "C" void kernel_launch(void* const* d_in, const int* in_sizes, int n_in,
                              void* d_out, int out_size)
{
    const float* x     = (const float*)d_in[0];
    const float* W     = (const float*)d_in[1];
    const float* b     = (const float*)d_in[2];
    const float* noise = (const float*)d_in[3];
    float* out = (float*)d_out;

    const int nTokens = in_sizes[3] / E_DIM;          // B*S from noise elem count
    const int writeIdx = (out_size >= nTokens * E_DIM + nTokens * 2) ? 1 : 0;

    const int grid = (nTokens + TOK_PER_BLK - 1) / TOK_PER_BLK;
    router_kernel<<<grid, BLOCK>>>(x, W, b, noise, out, nTokens, writeIdx);
}

// round 17
// speedup vs baseline: 1.0885x; 1.0885x over previous
#include <cuda_runtime.h>
#include <cuda_bf16.h>
#include <math.h>

// DynamicRouter: logits = x @ W^T + b + 0.1*noise ; top-2 ; sparse softmax.
// x[B=8,S=4096,D=768] f32, W[E=8,D=768] f32, b[8] f32, noise[B,S,8] f32.
//
// R17 (= R16 resubmit, canonical shared::cluster bulk-copy spelling):
// bulk-DMA streaming (cp.async.bulk + mbarrier), persistent 1 CTA/SM.
// Each warp double-buffers a contiguous 12KB 4-token slab via the bulk
// engine -- transfer-level tracking, not per-line MSHRs, to break the
// ~4TB/s plateau that pinned nine LDG-path variants at ~25us.

#define D_DIM        768
#define E_DIM        8
#define TOK_PER_WARP 4
#define WARPS        8
#define BLOCK        (WARPS * 32)
#define TOK_PER_BLK  (WARPS * TOK_PER_WARP)   // 32
#define D4           (D_DIM / 4)              // 192
#define NCHUNK       (D4 / 32)                // 6
#define SLAB_BYTES   (TOK_PER_WARP * D_DIM * 4)   // 12288
#define SW_BYTES     (E_DIM * D_DIM * 4)          // 24576
#define MBAR_OFF     SW_BYTES                     // 24576 (8 warps x 2 x 8B)
#define SLAB_OFF     25600                        // 1KB-aligned slab region
#define SMEM_BYTES   (SLAB_OFF + WARPS * 2 * SLAB_BYTES)  // 222208
#define GRID_CTAS    148
#define NOISE_STD    0.1f

__global__ __launch_bounds__(BLOCK, 1)
void router_kernel(const float* __restrict__ x,
                   const float* __restrict__ W,
                   const float* __restrict__ b,
                   const float* __restrict__ noise,
                   float* __restrict__ out,
                   int nTokens, int writeIdx)
{
    extern __shared__ char smem[];
    float4* sW4 = reinterpret_cast<float4*>(smem);   // 24KB, conflict-free stride
    const unsigned smem32 = (unsigned)__cvta_generic_to_shared(smem);

    const int tid  = threadIdx.x;
    const int lane = tid & 31;
    const int wid  = tid >> 5;

    // Stage W once per persistent CTA (coalesced float4 copy of 24 KB)
    {
        const float4* Wg = reinterpret_cast<const float4*>(W);
        #pragma unroll
        for (int i = 0; i < (E_DIM * D4) / BLOCK; i++)
            sW4[i * BLOCK + tid] = Wg[i * BLOCK + tid];
    }

    // Per-warp mbarriers (2 stages), init by lane 0
    if (lane == 0) {
        #pragma unroll
        for (int s = 0; s < 2; s++)
            asm volatile("mbarrier.init.shared.b64 [%0], 1;"
                         :: "r"(smem32 + MBAR_OFF + wid * 16 + s * 8) : "memory");
    }
    asm volatile("fence.proxy.async.shared::cta;" ::: "memory");
    __syncthreads();   // W visible + mbars initialized for the whole CTA

    const int nGroups = (nTokens + TOK_PER_BLK - 1) / TOK_PER_BLK;

    // clamped token base for group g (safe if nTokens % 32 != 0)
    auto baseOf = [&](int g) {
        int tb = g * TOK_PER_BLK + wid * TOK_PER_WARP;
        if (tb > nTokens - TOK_PER_WARP) tb = nTokens - TOK_PER_WARP;
        return tb;
    };

    // one bulk copy: 4 contiguous token rows (12 KB) -> this warp's stage s
    auto issueSlab = [&](int s, int g) {
        if (lane == 0) {
            const float* src = x + (size_t)baseOf(g) * D_DIM;
            const unsigned dst = smem32 + SLAB_OFF + (unsigned)(wid * 2 + s) * SLAB_BYTES;
            const unsigned mb  = smem32 + MBAR_OFF + wid * 16 + s * 8;
            asm volatile("mbarrier.arrive.expect_tx.shared.b64 _, [%0], %1;"
                         :: "r"(mb), "r"((unsigned)SLAB_BYTES) : "memory");
            asm volatile("cp.async.bulk.shared::cluster.global.mbarrier::complete_tx::bytes"
                         " [%0], [%1], %2, [%3];"
                         :: "r"(dst), "l"(src), "r"((unsigned)SLAB_BYTES), "r"(mb)
                         : "memory");
        }
    };

    auto waitSlab = [&](int s, unsigned parity) {
        const unsigned mb = smem32 + MBAR_OFF + wid * 16 + s * 8;
        unsigned done;
        asm volatile("{\n\t.reg .pred p;\n\t"
                     "mbarrier.try_wait.parity.acquire.cta.shared::cta.b64 p, [%1], %2;\n\t"
                     "selp.b32 %0, 1, 0, p;\n\t}"
                     : "=r"(done) : "r"(mb), "r"(parity) : "memory");
        if (!done) {
            asm volatile("{\n\t.reg .pred P1;\n\t"
                         "WL_%=:\n\t"
                         "mbarrier.try_wait.parity.acquire.cta.shared::cta.b64 P1, [%0], %1, 0x989680;\n\t"
                         "@P1 bra.uni WD_%=;\n\t"
                         "bra.uni WL_%=;\n\t"
                         "WD_%=:\n\t}"
                         :: "r"(mb), "r"(parity) : "memory");
        }
    };

    // prologue: slab for this CTA's first group
    if ((int)blockIdx.x < nGroups) issueSlab(0, blockIdx.x);

    int k = 0;
    for (int g = blockIdx.x; g < nGroups; g += gridDim.x, k++) {
        const int s = k & 1;
        const int gn = g + gridDim.x;
        if (gn < nGroups) issueSlab(1 - s, gn);     // 1-deep lookahead

        waitSlab(s, (unsigned)((k >> 1) & 1));

        const float4* slab = reinterpret_cast<const float4*>(
            smem + SLAB_OFF + (size_t)(wid * 2 + s) * SLAB_BYTES);

        float acc[TOK_PER_WARP * E_DIM];
        #pragma unroll
        for (int v = 0; v < TOK_PER_WARP * E_DIM; v++) acc[v] = 0.0f;

        #pragma unroll
        for (int c = 0; c < NCHUNK; c++) {
            float4 xv[TOK_PER_WARP];
            #pragma unroll
            for (int t = 0; t < TOK_PER_WARP; t++)
                xv[t] = slab[t * D4 + c * 32 + lane];    // conflict-free LDS.128
            const int p = c * 32 + lane;
            #pragma unroll
            for (int e = 0; e < E_DIM; e++) {
                const float4 wv = sW4[e * D4 + p];       // LDS.128, reused x4
                #pragma unroll
                for (int t = 0; t < TOK_PER_WARP; t++)
                    acc[t * E_DIM + e] += xv[t].x * wv.x + xv[t].y * wv.y
                                        + xv[t].z * wv.z + xv[t].w * wv.w;
            }
        }

        // Butterfly: lane l ends with the full 32-lane sum of slot v==l (v=t*8+e)
        #pragma unroll
        for (int m = 16; m >= 1; m >>= 1) {
            const bool upper = (lane & m) != 0;
            #pragma unroll
            for (int i = 0; i < m; i++) {
                const float lo = acc[i], hi = acc[i + m];
                const float send = upper ? lo : hi;
                const float recv = __shfl_xor_sync(0xFFFFFFFFu, send, m);
                acc[i] = upper ? (hi + recv) : (lo + recv);
            }
        }
        const float sum = acc[0];

        const int tb = baseOf(g);                  // matches slab contents
        const int t = lane >> 3;
        const int e = lane & 7;
        const long tok = (long)tb + t;
        const bool valid = tok < nTokens;

        const float nval = valid ? __ldg(noise + (size_t)tb * E_DIM + lane) : 0.0f;
        const float logit = sum + __ldg(b + e) + NOISE_STD * nval;

        // top-1 per 8-lane expert group (ties -> lower index, jax top_k order)
        float v1 = logit; int i1 = e;
        #pragma unroll
        for (int off = 1; off < 8; off <<= 1) {
            const float ov = __shfl_xor_sync(0xFFFFFFFFu, v1, off);
            const int   oi = __shfl_xor_sync(0xFFFFFFFFu, i1, off);
            if (ov > v1 || (ov == v1 && oi < i1)) { v1 = ov; i1 = oi; }
        }
        float v2 = (e == i1) ? -INFINITY : logit; int i2 = e;
        #pragma unroll
        for (int off = 1; off < 8; off <<= 1) {
            const float ov = __shfl_xor_sync(0xFFFFFFFFu, v2, off);
            const int   oi = __shfl_xor_sync(0xFFFFFFFFu, i2, off);
            if (ov > v2 || (ov == v2 && oi < i2)) { v2 = ov; i2 = oi; }
        }

        const float ed  = __expf(v2 - v1);
        const float inv = 1.0f / (1.0f + ed);
        const float p   = (e == i1) ? inv : ((e == i2) ? ed * inv : 0.0f);

        if (valid) {
            out[(size_t)tb * E_DIM + lane] = p;    // coalesced 128B per warp
            if (writeIdx && e == 0) {
                float* idxOut = out + (size_t)nTokens * E_DIM;
                idxOut[tok * 2 + 0] = (float)i1;
                idxOut[tok * 2 + 1] = (float)i2;
            }
        }
    }
}

extern "C" void kernel_launch(void* const* d_in, const int* in_sizes, int n_in,
                              void* d_out, int out_size)
{
    const float* x     = (const float*)d_in[0];
    const float* W     = (const float*)d_in[1];
    const float* b     = (const float*)d_in[2];
    const float* noise = (const float*)d_in[3];
    float* out = (float*)d_out;

    const int nTokens = in_sizes[3] / E_DIM;          // B*S from noise elem count
    const int writeIdx = (out_size >= nTokens * E_DIM + nTokens * 2) ? 1 : 0;

    // 217KB dynamic smem opt-in (idempotent; capture-safe)
    cudaFuncSetAttribute(router_kernel,
                         cudaFuncAttributeMaxDynamicSharedMemorySize,
                         SMEM_BYTES);

    router_kernel<<<GRID_CTAS, BLOCK, SMEM_BYTES>>>(x, W, b, noise, out,
                                                    nTokens, writeIdx);
}